// round 13
// baseline (speedup 1.0000x reference)
#include <cuda_runtime.h>
#include <cuda_fp16.h>
#include <cstdint>

// ---------------- problem dims ----------------
#define N_ROWS 32768
#define M_CENT 4096
#define D_DIM  32

#define BLOCK     256                    // 8 warps, warp = 16 rows
#define ROWS_CTA  128
#define NTILE     128                    // centers per tile (= one split)
#define NSPLIT    32
#define NRB       (N_ROWS / ROWS_CTA)    // 256 row blocks
#define TOTTILES  (NRB * NSPLIT)         // 8192 work tiles
#define NCTAS     592                    // 148 SMs x 4 CTAs -> single wave
#define NGRP      (NTILE / 8)
#define BSTRIDE   144                    // 128B payload + 16B pad (conflict-free LDSM)

#define SLOT_B    (NTILE * BSTRIDE)      // 18432
#define SLOT_YA   (NTILE * 8)            // 1024
#define SLOT      (SLOT_B + SLOT_YA)     // 19456
#define SMEM_TOT  (2 * SLOT)             // 38912 -> 4 CTAs/SM

// ---------------- device scratch ----------------
// per center, 128 B: [0,64) fp16 yh ; [64,128) fp16 yl  (y = yh + yl, exact to 2^-23)
__device__ uint8_t g_B[M_CENT * 128];
__device__ float2  g_ya[M_CENT];            // { -0.5*||ys||^2 , alpha }
__device__ float   g_part[NSPLIT * N_ROWS];

// ---------------- helpers ----------------
__device__ __forceinline__ uint32_t smem_u32(const void* p) {
    uint32_t a;
    asm("{ .reg .u64 t; cvta.to.shared.u64 t, %1; cvt.u32.u64 %0, t; }" : "=r"(a) : "l"(p));
    return a;
}
__device__ __forceinline__ float ex2f(float x) {
    float r; asm("ex2.approx.f32 %0, %1;" : "=f"(r) : "f"(x)); return r;
}
__device__ __forceinline__ void cp16(uint32_t dst, const void* src) {
    asm volatile("cp.async.cg.shared.global [%0], [%1], 16;" :: "r"(dst), "l"(src));
}
__device__ __forceinline__ void cp_commit() {
    asm volatile("cp.async.commit_group;" ::: "memory");
}
template <int N>
__device__ __forceinline__ void cp_wait() {
    asm volatile("cp.async.wait_group %0;" :: "n"(N) : "memory");
}
__device__ __forceinline__ void ldmx4(uint32_t* r, uint32_t addr) {
    asm volatile("ldmatrix.sync.aligned.m8n8.x4.shared.b16 {%0,%1,%2,%3}, [%4];"
                 : "=r"(r[0]), "=r"(r[1]), "=r"(r[2]), "=r"(r[3]) : "r"(addr));
}
// fp16 m16n8k16: D = A*B + C  (separate C: free bias / free zero-init)
__device__ __forceinline__ void mma_f16_c(float* d, const uint32_t* a, uint32_t b0, uint32_t b1,
                                          float c0, float c1, float c2, float c3) {
    asm volatile(
        "mma.sync.aligned.m16n8k16.row.col.f32.f16.f16.f32 "
        "{%0,%1,%2,%3}, {%4,%5,%6,%7}, {%8,%9}, {%10,%11,%12,%13};"
        : "=f"(d[0]), "=f"(d[1]), "=f"(d[2]), "=f"(d[3])
        : "r"(a[0]), "r"(a[1]), "r"(a[2]), "r"(a[3]), "r"(b0), "r"(b1),
          "f"(c0), "f"(c1), "f"(c2), "f"(c3));
}
// fp16 m16n8k16: D = A*B + D
__device__ __forceinline__ void mma_f16(float* d, const uint32_t* a, uint32_t b0, uint32_t b1) {
    asm volatile(
        "mma.sync.aligned.m16n8k16.row.col.f32.f16.f16.f32 "
        "{%0,%1,%2,%3}, {%4,%5,%6,%7}, {%8,%9}, {%0,%1,%2,%3};"
        : "+f"(d[0]), "+f"(d[1]), "+f"(d[2]), "+f"(d[3])
        : "r"(a[0]), "r"(a[1]), "r"(a[2]), "r"(a[3]), "r"(b0), "r"(b1));
}
__device__ __forceinline__ uint32_t pack_h2(float lo, float hi) {
    __half2 t = __floats2half2_rn(lo, hi);
    return *reinterpret_cast<uint32_t*>(&t);
}

// ---------------- prep: warp per center, y -> fp16 pair split ----------------
__global__ void prep_kernel(const float* __restrict__ centers,
                            const float* __restrict__ alphas,
                            const float* __restrict__ sigma) {
    const int m  = (blockIdx.x * blockDim.x + threadIdx.x) >> 5;
    const int ln = threadIdx.x & 31;                       // = dim k
    if (m >= M_CENT) return;
    const float g = sigma[0];
    const float c = sqrtf(1.44269504088896340736f / (g * g));   // sqrt(log2e)/g
    float v = centers[m * D_DIM + ln] * c;
    __half yh = __float2half_rn(v);
    __half yl = __float2half_rn(v - __half2float(yh));     // residual fits fp16 (2^-23 total)
    reinterpret_cast<__half*>(g_B + (size_t)m * 128)[ln]      = yh;
    reinterpret_cast<__half*>(g_B + (size_t)m * 128 + 64)[ln] = yl;
    float y2 = v * v;
#pragma unroll
    for (int o = 16; o; o >>= 1) y2 += __shfl_xor_sync(0xFFFFFFFFu, y2, o);
    if (ln == 0) g_ya[m] = make_float2(-0.5f * y2, alphas[m]);
}

// ---------------- B tile loader: tile T -> ring slot ----------------
__device__ __forceinline__ void load_btile(uint32_t sb, int slot, int T, int tid) {
    const int split = T & (NSPLIT - 1);
    const uint8_t* src = g_B + (size_t)split * NTILE * 128;
    const uint32_t bd = sb + slot * SLOT;
#pragma unroll
    for (int i = 0; i < 4; i++) {
        int idx = tid + i * BLOCK;          // 0..1023 16B chunks (8 per center)
        int cc = idx >> 3, rr = idx & 7;
        cp16(bd + cc * BSTRIDE + rr * 16, src + idx * 16);
    }
    if (tid < 64) {
        const char* ys = reinterpret_cast<const char*>(g_ya + split * NTILE);
        cp16(bd + SLOT_B + tid * 16, ys + tid * 16);
    }
}

// ---------------- main kernel: persistent, 2 independent depth-2 MMA chains ----------------
__global__ void __launch_bounds__(BLOCK, 4)
rbf_main(const float* __restrict__ X,
         const float* __restrict__ sigma) {
    extern __shared__ char smem[];
    const uint32_t sb = smem_u32(smem);
    const int tid  = threadIdx.x;
    const int w    = tid >> 5;
    const int ln   = tid & 31;
    const int gID  = ln >> 2;
    const int qid  = ln & 3;
    const int row0 = w * 16 + gID;      // CTA-local rows: row0, row0+8
    const int row1 = row0 + 8;

    const float g = __ldg(sigma);
    const float c = sqrtf(1.44269504088896340736f / (g * g));

    const int cta = blockIdx.x;
    const int loT = (int)(((long long)cta * TOTTILES) / NCTAS);
    const int hiT = (int)(((long long)(cta + 1) * TOTTILES) / NCTAS);
    const int n   = hiT - loT;

    load_btile(sb, 0, loT, tid);
    cp_commit();
    if (n > 1) load_btile(sb, 1, loT + 1, tid);
    cp_commit();

    const uint32_t blane = (uint32_t)((ln & 7) * BSTRIDE + (ln >> 3) * 16);

    uint32_t aH[2][4];   // fp16 A frags: kstep 0 (dims 0-15), kstep 1 (dims 16-31)
    float ex0 = 1.f, ex1 = 1.f;
    int curRb = -1;

    for (int i = 0; i < n; i++) {
        const int T  = loT + i;
        const int rb = T >> 5;

        cp_wait<1>();
        __syncthreads();

        // ---- A fragments straight from global X (fp16 single-rounded) ----
        if (rb != curRb) {
            curRb = rb;
            float s[2];
#pragma unroll
            for (int j = 0; j < 2; j++) {                 // j=0 -> row0, j=1 -> row1
                const int grow = rb * ROWS_CTA + (j ? row1 : row0);
                const float* rp = X + (size_t)grow * D_DIM;
                float2 u0 = *reinterpret_cast<const float2*>(rp + 2 * qid);
                float2 u1 = *reinterpret_cast<const float2*>(rp + 2 * qid + 8);
                float2 u2 = *reinterpret_cast<const float2*>(rp + 2 * qid + 16);
                float2 u3 = *reinterpret_cast<const float2*>(rp + 2 * qid + 24);
                u0.x *= c; u0.y *= c; u1.x *= c; u1.y *= c;
                u2.x *= c; u2.y *= c; u3.x *= c; u3.y *= c;
                s[j] = u0.x*u0.x + u0.y*u0.y + u1.x*u1.x + u1.y*u1.y
                     + u2.x*u2.x + u2.y*u2.y + u3.x*u3.x + u3.y*u3.y;
                aH[0][0 + j] = pack_h2(u0.x, u0.y);
                aH[0][2 + j] = pack_h2(u1.x, u1.y);
                aH[1][0 + j] = pack_h2(u2.x, u2.y);
                aH[1][2 + j] = pack_h2(u3.x, u3.y);
            }
            s[0] += __shfl_xor_sync(0xFFFFFFFFu, s[0], 1);
            s[0] += __shfl_xor_sync(0xFFFFFFFFu, s[0], 2);
            s[1] += __shfl_xor_sync(0xFFFFFFFFu, s[1], 1);
            s[1] += __shfl_xor_sync(0xFFFFFFFFu, s[1], 2);
            ex0 = ex2f(-0.5f * s[0]);
            ex1 = ex2f(-0.5f * s[1]);
        }

        // ---- consume tile i from slot i&1 ----
        const uint32_t Bb  = sb + (i & 1) * SLOT + blane;
        const char*    yab = smem + (i & 1) * SLOT + SLOT_B;

        float acc0 = 0.f, acc1 = 0.f;
#pragma unroll
        for (int gi = 0; gi < NGRP; gi++) {
            const uint32_t gb = Bb + gi * (8 * BSTRIDE);
            uint32_t p[4], r[4];
            ldmx4(p, gb);          // yh k0-31 (8 centers)
            ldmx4(r, gb + 64);     // yl k0-31
            float4 ya = *reinterpret_cast<const float4*>(yab + gi * 64 + qid * 16);

            // two INDEPENDENT depth-2 accumulator chains (breaks MMA RAW serialization)
            float dP[4], dQ[4];
            mma_f16_c(dP, aH[0], p[0], p[1], ya.x, ya.z, ya.x, ya.z);   // xh.yh k0-15 + bias
            mma_f16_c(dQ, aH[0], r[0], r[1], 0.f, 0.f, 0.f, 0.f);      // xh.yl k0-15
            mma_f16  (dP, aH[1], p[2], p[3]);                           // xh.yh k16-31
            mma_f16  (dQ, aH[1], r[2], r[3]);                           // xh.yl k16-31

            acc0 = fmaf(ex2f(dP[0] + dQ[0]), ya.y, acc0);
            acc0 = fmaf(ex2f(dP[1] + dQ[1]), ya.w, acc0);
            acc1 = fmaf(ex2f(dP[2] + dQ[2]), ya.y, acc1);
            acc1 = fmaf(ex2f(dP[3] + dQ[3]), ya.w, acc1);
        }

        __syncthreads();
        if (i + 2 < n) load_btile(sb, i & 1, T + 2, tid);
        cp_commit();

        acc0 += __shfl_xor_sync(0xFFFFFFFFu, acc0, 1);
        acc0 += __shfl_xor_sync(0xFFFFFFFFu, acc0, 2);
        acc1 += __shfl_xor_sync(0xFFFFFFFFu, acc1, 1);
        acc1 += __shfl_xor_sync(0xFFFFFFFFu, acc1, 2);
        if (qid == 0) {
            float* dst = g_part + (size_t)(T & (NSPLIT - 1)) * N_ROWS + rb * ROWS_CTA;
            dst[row0] = acc0 * ex0;
            dst[row1] = acc1 * ex1;
        }
    }
}

// ---------------- final reduce over 32 splits ----------------
__global__ void reduce_kernel(float* __restrict__ out) {
    const int nidx = blockIdx.x * blockDim.x + threadIdx.x;
    float s = 0.f;
#pragma unroll
    for (int i = 0; i < NSPLIT; i++) s += g_part[(size_t)i * N_ROWS + nidx];
    out[nidx] = s;
}

// ---------------- launch ----------------
extern "C" void kernel_launch(void* const* d_in, const int* in_sizes, int n_in,
                              void* d_out, int out_size) {
    const float* X       = (const float*)d_in[0];
    const float* centers = (const float*)d_in[1];
    const float* alphas  = (const float*)d_in[2];
    const float* sigma   = (const float*)d_in[3];
    float* out = (float*)d_out;

    cudaFuncSetAttribute(rbf_main, cudaFuncAttributeMaxDynamicSharedMemorySize, SMEM_TOT);

    prep_kernel<<<M_CENT / 8, 256>>>(centers, alphas, sigma);
    rbf_main<<<NCTAS, BLOCK, SMEM_TOT>>>(X, sigma);
    reduce_kernel<<<N_ROWS / 256, 256>>>(out);
}

// round 14
// speedup vs baseline: 1.1475x; 1.1475x over previous
#include <cuda_runtime.h>
#include <cuda_fp16.h>
#include <cstdint>

// ---------------- problem dims ----------------
#define N_ROWS 32768
#define M_CENT 4096
#define D_DIM  32

#define BLOCK     256                    // 8 warps; warp = 2 x m16 tiles = 32 rows
#define ROWS_CTA  256
#define NTILE     128                    // centers per tile (= one split)
#define NSPLIT    32
#define NRB       (N_ROWS / ROWS_CTA)    // 128 row blocks
#define TOTTILES  (NRB * NSPLIT)         // 4096 work tiles
#define NCTAS     444                    // 148 SMs x 3 CTAs -> single wave
#define NGRP      (NTILE / 8)
#define BSTRIDE   144                    // 128B payload + 16B pad (conflict-free LDSM)

#define SLOT_B    (NTILE * BSTRIDE)      // 18432
#define SLOT_YA   (NTILE * 8)            // 1024
#define SLOT      (SLOT_B + SLOT_YA)     // 19456
#define SMEM_TOT  (2 * SLOT)             // 38912

// ---------------- device scratch ----------------
// per center, 128 B: [0,64) fp16 yh ; [64,128) fp16 yl  (y = yh + yl, exact to 2^-23)
__device__ uint8_t g_B[M_CENT * 128];
__device__ float2  g_ya[M_CENT];            // { -0.5*||ys||^2 , alpha }
__device__ float   g_part[NSPLIT * N_ROWS];

// ---------------- helpers ----------------
__device__ __forceinline__ uint32_t smem_u32(const void* p) {
    uint32_t a;
    asm("{ .reg .u64 t; cvta.to.shared.u64 t, %1; cvt.u32.u64 %0, t; }" : "=r"(a) : "l"(p));
    return a;
}
__device__ __forceinline__ float ex2f(float x) {
    float r; asm("ex2.approx.f32 %0, %1;" : "=f"(r) : "f"(x)); return r;
}
__device__ __forceinline__ void cp16(uint32_t dst, const void* src) {
    asm volatile("cp.async.cg.shared.global [%0], [%1], 16;" :: "r"(dst), "l"(src));
}
__device__ __forceinline__ void cp_commit() {
    asm volatile("cp.async.commit_group;" ::: "memory");
}
template <int N>
__device__ __forceinline__ void cp_wait() {
    asm volatile("cp.async.wait_group %0;" :: "n"(N) : "memory");
}
__device__ __forceinline__ void ldmx4(uint32_t* r, uint32_t addr) {
    asm volatile("ldmatrix.sync.aligned.m8n8.x4.shared.b16 {%0,%1,%2,%3}, [%4];"
                 : "=r"(r[0]), "=r"(r[1]), "=r"(r[2]), "=r"(r[3]) : "r"(addr));
}
// fp16 m16n8k16: D = A*B + C  (separate C: free bias)
__device__ __forceinline__ void mma_f16_c(float* d, const uint32_t* a, uint32_t b0, uint32_t b1,
                                          float c0, float c1, float c2, float c3) {
    asm volatile(
        "mma.sync.aligned.m16n8k16.row.col.f32.f16.f16.f32 "
        "{%0,%1,%2,%3}, {%4,%5,%6,%7}, {%8,%9}, {%10,%11,%12,%13};"
        : "=f"(d[0]), "=f"(d[1]), "=f"(d[2]), "=f"(d[3])
        : "r"(a[0]), "r"(a[1]), "r"(a[2]), "r"(a[3]), "r"(b0), "r"(b1),
          "f"(c0), "f"(c1), "f"(c2), "f"(c3));
}
// fp16 m16n8k16: D = A*B + D
__device__ __forceinline__ void mma_f16(float* d, const uint32_t* a, uint32_t b0, uint32_t b1) {
    asm volatile(
        "mma.sync.aligned.m16n8k16.row.col.f32.f16.f16.f32 "
        "{%0,%1,%2,%3}, {%4,%5,%6,%7}, {%8,%9}, {%0,%1,%2,%3};"
        : "+f"(d[0]), "+f"(d[1]), "+f"(d[2]), "+f"(d[3])
        : "r"(a[0]), "r"(a[1]), "r"(a[2]), "r"(a[3]), "r"(b0), "r"(b1));
}
__device__ __forceinline__ uint32_t pack_h2(float lo, float hi) {
    __half2 t = __floats2half2_rn(lo, hi);
    return *reinterpret_cast<uint32_t*>(&t);
}

// ---------------- prep: warp per center, y -> fp16 pair split ----------------
__global__ void prep_kernel(const float* __restrict__ centers,
                            const float* __restrict__ alphas,
                            const float* __restrict__ sigma) {
    const int m  = (blockIdx.x * blockDim.x + threadIdx.x) >> 5;
    const int ln = threadIdx.x & 31;                       // = dim k
    if (m >= M_CENT) return;
    const float g = sigma[0];
    const float c = sqrtf(1.44269504088896340736f / (g * g));   // sqrt(log2e)/g
    float v = centers[m * D_DIM + ln] * c;
    __half yh = __float2half_rn(v);
    __half yl = __float2half_rn(v - __half2float(yh));     // residual (exact to ~2^-23)
    reinterpret_cast<__half*>(g_B + (size_t)m * 128)[ln]      = yh;
    reinterpret_cast<__half*>(g_B + (size_t)m * 128 + 64)[ln] = yl;
    float y2 = v * v;
#pragma unroll
    for (int o = 16; o; o >>= 1) y2 += __shfl_xor_sync(0xFFFFFFFFu, y2, o);
    if (ln == 0) g_ya[m] = make_float2(-0.5f * y2, alphas[m]);
}

// ---------------- B tile loader: tile T -> ring slot ----------------
__device__ __forceinline__ void load_btile(uint32_t sb, int slot, int T, int tid) {
    const int split = T & (NSPLIT - 1);
    const uint8_t* src = g_B + (size_t)split * NTILE * 128;
    const uint32_t bd = sb + slot * SLOT;
#pragma unroll
    for (int i = 0; i < 4; i++) {
        int idx = tid + i * BLOCK;          // 0..1023 16B chunks (8 per center)
        int cc = idx >> 3, rr = idx & 7;
        cp16(bd + cc * BSTRIDE + rr * 16, src + idx * 16);
    }
    if (tid < 64) {
        const char* ys = reinterpret_cast<const char*>(g_ya + split * NTILE);
        cp16(bd + SLOT_B + tid * 16, ys + tid * 16);
    }
}

// ---------------- A-fragment builder: one m16 tile (fp16) ----------------
__device__ __forceinline__ void build_afrag(const float* __restrict__ X, int rowA, int rowB,
                                            int qid, float c, uint32_t aH[2][4],
                                            float& exA, float& exB) {
    float s[2];
#pragma unroll
    for (int j = 0; j < 2; j++) {
        const float* rp = X + (size_t)(j ? rowB : rowA) * D_DIM;
        float2 u0 = *reinterpret_cast<const float2*>(rp + 2 * qid);
        float2 u1 = *reinterpret_cast<const float2*>(rp + 2 * qid + 8);
        float2 u2 = *reinterpret_cast<const float2*>(rp + 2 * qid + 16);
        float2 u3 = *reinterpret_cast<const float2*>(rp + 2 * qid + 24);
        u0.x *= c; u0.y *= c; u1.x *= c; u1.y *= c;
        u2.x *= c; u2.y *= c; u3.x *= c; u3.y *= c;
        s[j] = u0.x*u0.x + u0.y*u0.y + u1.x*u1.x + u1.y*u1.y
             + u2.x*u2.x + u2.y*u2.y + u3.x*u3.x + u3.y*u3.y;
        aH[0][0 + j] = pack_h2(u0.x, u0.y);
        aH[0][2 + j] = pack_h2(u1.x, u1.y);
        aH[1][0 + j] = pack_h2(u2.x, u2.y);
        aH[1][2 + j] = pack_h2(u3.x, u3.y);
    }
    s[0] += __shfl_xor_sync(0xFFFFFFFFu, s[0], 1);
    s[0] += __shfl_xor_sync(0xFFFFFFFFu, s[0], 2);
    s[1] += __shfl_xor_sync(0xFFFFFFFFu, s[1], 1);
    s[1] += __shfl_xor_sync(0xFFFFFFFFu, s[1], 2);
    exA = ex2f(-0.5f * s[0]);
    exB = ex2f(-0.5f * s[1]);
}

// ---------------- main kernel: persistent; warp owns 2 m16 tiles; 8 MMAs reuse 2 LDSMs ----------------
__global__ void __launch_bounds__(BLOCK, 3)
rbf_main(const float* __restrict__ X,
         const float* __restrict__ sigma) {
    extern __shared__ char smem[];
    const uint32_t sb = smem_u32(smem);
    const int tid  = threadIdx.x;
    const int w    = tid >> 5;
    const int ln   = tid & 31;
    const int gID  = ln >> 2;
    const int qid  = ln & 3;
    const int row0 = w * 16 + gID;      // tile-0 rows: row0, row0+8
    const int row2 = row0 + 128;        // tile-1 rows: row2, row2+8

    const float g = __ldg(sigma);
    const float c = sqrtf(1.44269504088896340736f / (g * g));

    const int cta = blockIdx.x;
    const int loT = (int)(((long long)cta * TOTTILES) / NCTAS);
    const int hiT = (int)(((long long)(cta + 1) * TOTTILES) / NCTAS);
    const int n   = hiT - loT;

    load_btile(sb, 0, loT, tid);
    cp_commit();
    if (n > 1) load_btile(sb, 1, loT + 1, tid);
    cp_commit();

    const uint32_t blane = (uint32_t)((ln & 7) * BSTRIDE + (ln >> 3) * 16);

    uint32_t aH0[2][4], aH1[2][4];     // fp16 A frags for the two row tiles
    float ex0 = 1.f, ex1 = 1.f, ex2v = 1.f, ex3 = 1.f;
    int curRb = -1;

    for (int i = 0; i < n; i++) {
        const int T  = loT + i;
        const int rb = T >> 5;

        cp_wait<1>();
        __syncthreads();

        if (rb != curRb) {
            curRb = rb;
            const int base = rb * ROWS_CTA;
            build_afrag(X, base + row0, base + row0 + 8, qid, c, aH0, ex0, ex1);
            build_afrag(X, base + row2, base + row2 + 8, qid, c, aH1, ex2v, ex3);
        }

        // ---- consume tile i from slot i&1 ----
        const uint32_t Bb  = sb + (i & 1) * SLOT + blane;
        const char*    yab = smem + (i & 1) * SLOT + SLOT_B;

        float acc0 = 0.f, acc1 = 0.f, acc2 = 0.f, acc3 = 0.f;
#pragma unroll
        for (int gi = 0; gi < NGRP; gi++) {
            const uint32_t gb = Bb + gi * (8 * BSTRIDE);
            uint32_t p[4], r[4];
            ldmx4(p, gb);          // yh k0-31 (8 centers)
            ldmx4(r, gb + 64);     // yl k0-31
            float4 ya = *reinterpret_cast<const float4*>(yab + gi * 64 + qid * 16);

            // two natural independent serial chains (one per row tile), bias-in-C
            float dP[4], dQ[4];
            mma_f16_c(dP, aH0[0], p[0], p[1], ya.x, ya.z, ya.x, ya.z);  // t0: xh.yh k0-15 + bias
            mma_f16_c(dQ, aH1[0], p[0], p[1], ya.x, ya.z, ya.x, ya.z);  // t1: xh.yh k0-15 + bias
            mma_f16  (dP, aH0[1], p[2], p[3]);                           // t0: xh.yh k16-31
            mma_f16  (dQ, aH1[1], p[2], p[3]);                           // t1
            mma_f16  (dP, aH0[0], r[0], r[1]);                           // t0: xh.yl k0-15
            mma_f16  (dQ, aH1[0], r[0], r[1]);                           // t1
            mma_f16  (dP, aH0[1], r[2], r[3]);                           // t0: xh.yl k16-31
            mma_f16  (dQ, aH1[1], r[2], r[3]);                           // t1

            acc0 = fmaf(ex2f(dP[0]), ya.y, acc0);
            acc0 = fmaf(ex2f(dP[1]), ya.w, acc0);
            acc1 = fmaf(ex2f(dP[2]), ya.y, acc1);
            acc1 = fmaf(ex2f(dP[3]), ya.w, acc1);
            acc2 = fmaf(ex2f(dQ[0]), ya.y, acc2);
            acc2 = fmaf(ex2f(dQ[1]), ya.w, acc2);
            acc3 = fmaf(ex2f(dQ[2]), ya.y, acc3);
            acc3 = fmaf(ex2f(dQ[3]), ya.w, acc3);
        }

        __syncthreads();
        if (i + 2 < n) load_btile(sb, i & 1, T + 2, tid);
        cp_commit();

        acc0 += __shfl_xor_sync(0xFFFFFFFFu, acc0, 1);
        acc0 += __shfl_xor_sync(0xFFFFFFFFu, acc0, 2);
        acc1 += __shfl_xor_sync(0xFFFFFFFFu, acc1, 1);
        acc1 += __shfl_xor_sync(0xFFFFFFFFu, acc1, 2);
        acc2 += __shfl_xor_sync(0xFFFFFFFFu, acc2, 1);
        acc2 += __shfl_xor_sync(0xFFFFFFFFu, acc2, 2);
        acc3 += __shfl_xor_sync(0xFFFFFFFFu, acc3, 1);
        acc3 += __shfl_xor_sync(0xFFFFFFFFu, acc3, 2);
        if (qid == 0) {
            float* dst = g_part + (size_t)(T & (NSPLIT - 1)) * N_ROWS + rb * ROWS_CTA;
            dst[row0]      = acc0 * ex0;
            dst[row0 + 8]  = acc1 * ex1;
            dst[row2]      = acc2 * ex2v;
            dst[row2 + 8]  = acc3 * ex3;
        }
    }
}

// ---------------- final reduce over 32 splits ----------------
__global__ void reduce_kernel(float* __restrict__ out) {
    const int nidx = blockIdx.x * blockDim.x + threadIdx.x;
    float s = 0.f;
#pragma unroll
    for (int i = 0; i < NSPLIT; i++) s += g_part[(size_t)i * N_ROWS + nidx];
    out[nidx] = s;
}

// ---------------- launch ----------------
extern "C" void kernel_launch(void* const* d_in, const int* in_sizes, int n_in,
                              void* d_out, int out_size) {
    const float* X       = (const float*)d_in[0];
    const float* centers = (const float*)d_in[1];
    const float* alphas  = (const float*)d_in[2];
    const float* sigma   = (const float*)d_in[3];
    float* out = (float*)d_out;

    cudaFuncSetAttribute(rbf_main, cudaFuncAttributeMaxDynamicSharedMemorySize, SMEM_TOT);

    prep_kernel<<<M_CENT / 8, 256>>>(centers, alphas, sigma);
    rbf_main<<<NCTAS, BLOCK, SMEM_TOT>>>(X, sigma);
    reduce_kernel<<<N_ROWS / 256, 256>>>(out);
}